// round 6
// baseline (speedup 1.0000x reference)
#include <cuda_runtime.h>
#include <cuda_fp16.h>
#include <cstdint>
#include <cstddef>

// ---------------- problem dims (fixed by the dataset instance) ----------------
#define BLOCK   128
#define EMBED   4096
#define HIDDEN  16384
#define OUTD    4096
#define NZB     32
#define MACT    (NZB * BLOCK)   // 4096 active rows

// ---------------- scratch (device globals: allocation-free rule) -------------
__device__ __half d_g  [(size_t)MACT   * EMBED ];  // gathered activations fp16 [M,K]
__device__ __half d_w1t[(size_t)HIDDEN * EMBED ];  // fc1^T fp16 [N=HIDDEN, K=EMBED]
__device__ __half d_w2t[(size_t)OUTD   * HIDDEN];  // fc2^T fp16 [N=OUTD,   K=HIDDEN]
__device__ __half d_h  [(size_t)MACT   * HIDDEN];  // hidden fp16 [M,K2]

// ---------------- PTX helpers (all portable, sm_80-level) ---------------------
__device__ __forceinline__ uint32_t smem_u32(const void* p) {
    uint32_t a;
    asm("{ .reg .u64 t; cvta.to.shared.u64 t, %1; cvt.u32.u64 %0, t; }" : "=r"(a) : "l"(p));
    return a;
}
__device__ __forceinline__ void cp16(uint32_t dst, const void* src) {
    asm volatile("cp.async.cg.shared.global [%0], [%1], 16;" :: "r"(dst), "l"(src) : "memory");
}
#define CP_COMMIT()  asm volatile("cp.async.commit_group;" ::: "memory")
#define CP_WAIT1()   asm volatile("cp.async.wait_group 1;" ::: "memory")
#define SW128(o) ((o) ^ (((o) >> 3) & 0x70))

__device__ __forceinline__ void ldsm_x4(uint32_t* r, uint32_t addr) {
    asm volatile("ldmatrix.sync.aligned.m8n8.x4.shared.b16 {%0,%1,%2,%3}, [%4];"
                 : "=r"(r[0]), "=r"(r[1]), "=r"(r[2]), "=r"(r[3]) : "r"(addr));
}
__device__ __forceinline__ void ldsm_x2(uint32_t* r, uint32_t addr) {
    asm volatile("ldmatrix.sync.aligned.m8n8.x2.shared.b16 {%0,%1}, [%2];"
                 : "=r"(r[0]), "=r"(r[1]) : "r"(addr));
}
__device__ __forceinline__ void mma16816(float* c, const uint32_t* a, const uint32_t* b) {
    asm volatile(
        "mma.sync.aligned.m16n8k16.row.col.f32.f16.f16.f32 "
        "{%0,%1,%2,%3}, {%4,%5,%6,%7}, {%8,%9}, {%0,%1,%2,%3};"
        : "+f"(c[0]), "+f"(c[1]), "+f"(c[2]), "+f"(c[3])
        : "r"(a[0]), "r"(a[1]), "r"(a[2]), "r"(a[3]), "r"(b[0]), "r"(b[1]));
}

// ---------------- conversion kernels -----------------------------------------
__global__ void gather_convert(const float* __restrict__ x, const int* __restrict__ nz,
                               __half* __restrict__ g) {
    size_t idx  = (size_t)blockIdx.x * blockDim.x + threadIdx.x;  // over MACT*EMBED/4
    int    row  = (int)(idx >> 10);            // EMBED/4 = 1024 float4 per row
    int    col4 = (int)(idx & 1023);
    int    blk  = row >> 7;
    int    srow = nz[blk] * BLOCK + (row & 127);
    float4 v = reinterpret_cast<const float4*>(x)[(size_t)srow * (EMBED / 4) + col4];
    __half2* dst = reinterpret_cast<__half2*>(g + (size_t)row * EMBED + (size_t)col4 * 4);
    dst[0] = __floats2half2_rn(v.x, v.y);
    dst[1] = __floats2half2_rn(v.z, v.w);
}

// in [R,C] fp32 row-major -> out [C,R] fp16 row-major
__global__ void transpose_convert(const float* __restrict__ in, __half* __restrict__ out,
                                  int R, int C) {
    __shared__ float tile[32][33];
    int c0 = blockIdx.x * 32, r0 = blockIdx.y * 32;
    int tx = threadIdx.x, ty = threadIdx.y;  // (32,8)
#pragma unroll
    for (int i = 0; i < 4; i++) {
        int y = ty + i * 8;
        tile[y][tx] = in[(size_t)(r0 + y) * C + c0 + tx];
    }
    __syncthreads();
#pragma unroll
    for (int i = 0; i < 4; i++) {
        int y = ty + i * 8;
        out[(size_t)(c0 + y) * R + r0 + tx] = __float2half(tile[tx][y]);
    }
}

// ---------------- HMMA GEMM ---------------------------------------------------
// C[m,n] = sum_k A[m,k]*B[n,k]; A:[M,KTOT] fp16 K-major, B:[Ntot,KTOT] fp16 K-major.
// Grid: blockIdx.x = M-tile (fast), blockIdx.y = N-tile (slow) -> a 148-CTA wave
// shares ~5 B tiles + all A tiles through L2 (DRAM traffic ~once per operand).
// CTA tile 128x128, BK=64 (SW128 rows), 3-stage cp.async, 2 CTAs/SM.
// 8 warps in a 2(m) x 4(n) grid; warp tile 64x32; mma.sync m16n8k16.
constexpr int BM = 128, BN = 128, BK = 64, STAGES = 3;
constexpr uint32_t ABYTES      = BM * BK * 2;          // 16384
constexpr uint32_t STAGE_BYTES = 2 * ABYTES;           // 32768
constexpr uint32_t SMEM_DYN    = STAGES * STAGE_BYTES; // 98304

template <int KTOT, int LDC, bool SCATTER>
__global__ void __launch_bounds__(256, 2)
gemm_f16(const __half* __restrict__ A, const __half* __restrict__ B,
         void* __restrict__ C, const int* __restrict__ nz) {
    extern __shared__ char smem[];
    const uint32_t sb = smem_u32(smem);
    const int tid  = threadIdx.x;
    const int lane = tid & 31, wid = tid >> 5;
    const int wm = wid >> 2, wn = wid & 3;             // 2 x 4 warp grid
    const int m0 = blockIdx.x * BM, n0 = blockIdx.y * BN;   // m-fast grid
    constexpr int KIT = KTOT / BK;

    // per-thread cp.async geometry: thread t covers row t/2, 64B half-row t%2
    const int lrow = tid >> 1;
    const int lcol = (tid & 1) * 64;                   // byte offset in 128B row
    const char* gA = (const char*)(A + (size_t)(m0 + lrow) * KTOT) + lcol;
    const char* gB = (const char*)(B + (size_t)(n0 + lrow) * KTOT) + lcol;
    const uint32_t swb = (uint32_t)(lrow * 128 + lcol);

    float acc[4][4][4];
#pragma unroll
    for (int i = 0; i < 4; i++)
#pragma unroll
        for (int j = 0; j < 4; j++)
#pragma unroll
            for (int q = 0; q < 4; q++) acc[i][j][q] = 0.f;

    // prologue: fill stages 0..1 (2 commits)
#pragma unroll
    for (int s = 0; s < STAGES - 1; s++) {
        const uint32_t st = sb + (uint32_t)s * STAGE_BYTES;
        const size_t ko = (size_t)s * (BK * 2);
#pragma unroll
        for (int ch = 0; ch < 4; ch++)
            cp16(st + SW128(swb + ch * 16), gA + ko + ch * 16);
#pragma unroll
        for (int ch = 0; ch < 4; ch++)
            cp16(st + ABYTES + SW128(swb + ch * 16), gB + ko + ch * 16);
        CP_COMMIT();
    }

    for (int it = 0; it < KIT; it++) {
        // groups committed: 2+it; pending<=1 -> stages 0..it resident
        CP_WAIT1();
        __syncthreads();

        // issue stage it+2 into slot (it+2)%3 (compute uses slot it%3; the
        // overwritten stage it-1 was fully consumed before the barrier above)
        const int ls = it + STAGES - 1;
        if (ls < KIT) {
            const uint32_t st = sb + (uint32_t)(ls % STAGES) * STAGE_BYTES;
            const size_t ko = (size_t)ls * (BK * 2);
#pragma unroll
            for (int ch = 0; ch < 4; ch++)
                cp16(st + SW128(swb + ch * 16), gA + ko + ch * 16);
#pragma unroll
            for (int ch = 0; ch < 4; ch++)
                cp16(st + ABYTES + SW128(swb + ch * 16), gB + ko + ch * 16);
        }
        CP_COMMIT();

        const uint32_t sA  = sb + (uint32_t)(it % STAGES) * STAGE_BYTES;
        const uint32_t sBs = sA + ABYTES;
#pragma unroll
        for (int ks = 0; ks < 4; ks++) {
            uint32_t a[4][4], b[4][2];
#pragma unroll
            for (int i = 0; i < 4; i++) {
                const uint32_t r  = (uint32_t)(wm * 64 + i * 16 + (lane & 15));
                const uint32_t cb = (uint32_t)(ks * 32 + ((lane >> 4) << 4));
                ldsm_x4(a[i], sA + SW128(r * 128 + cb));
            }
#pragma unroll
            for (int j = 0; j < 4; j++) {
                const uint32_t r  = (uint32_t)(wn * 32 + j * 8 + (lane & 7));
                const uint32_t cb = (uint32_t)(ks * 32 + (((lane >> 3) & 1) << 4));
                ldsm_x2(b[j], sBs + SW128(r * 128 + cb));
            }
#pragma unroll
            for (int i = 0; i < 4; i++)
#pragma unroll
                for (int j = 0; j < 4; j++)
                    mma16816(acc[i][j], a[i], b[j]);
        }
    }

    // ---------------- epilogue ----------------
    // thread (i,j) frag: rows wm*64+i*16+lane/4 (+8), cols wn*32+j*8+2*(lane%4)
    const int rbase = wm * 64 + (lane >> 2);
    const int cbase = n0 + wn * 32 + 2 * (lane & 3);
    if (!SCATTER) {
        __half* Ch = (__half*)C;
#pragma unroll
        for (int i = 0; i < 4; i++) {
#pragma unroll
            for (int j = 0; j < 4; j++) {
                const int col = cbase + j * 8;
                const size_t r0 = (size_t)(m0 + rbase + i * 16) * LDC + col;
                const size_t r1 = r0 + (size_t)8 * LDC;
                *reinterpret_cast<__half2*>(Ch + r0) =
                    __floats2half2_rn(acc[i][j][0], acc[i][j][1]);
                *reinterpret_cast<__half2*>(Ch + r1) =
                    __floats2half2_rn(acc[i][j][2], acc[i][j][3]);
            }
        }
    } else {
        float* Cf = (float*)C;
        const int orow = nz[blockIdx.x] * BLOCK;   // m-tile (blockIdx.x) == source block
#pragma unroll
        for (int i = 0; i < 4; i++) {
#pragma unroll
            for (int j = 0; j < 4; j++) {
                const int col = cbase + j * 8;
                const size_t r0 = (size_t)(orow + rbase + i * 16) * LDC + col;
                const size_t r1 = r0 + (size_t)8 * LDC;
                *reinterpret_cast<float2*>(Cf + r0) =
                    make_float2(acc[i][j][0], acc[i][j][1]);
                *reinterpret_cast<float2*>(Cf + r1) =
                    make_float2(acc[i][j][2], acc[i][j][3]);
            }
        }
    }
}

// ---------------- launch ------------------------------------------------------
extern "C" void kernel_launch(void* const* d_in, const int* in_sizes, int n_in,
                              void* d_out, int out_size) {
    const float* x   = (const float*)d_in[0];
    const float* fc1 = (const float*)d_in[1];
    const float* fc2 = (const float*)d_in[2];
    const int*   nz  = (const int*)d_in[3];
    (void)in_sizes; (void)n_in;

    void *pg, *pw1, *pw2, *ph;
    cudaGetSymbolAddress(&pg,  d_g);
    cudaGetSymbolAddress(&pw1, d_w1t);
    cudaGetSymbolAddress(&pw2, d_w2t);
    cudaGetSymbolAddress(&ph,  d_h);

    cudaFuncSetAttribute(gemm_f16<EMBED, HIDDEN, false>,
                         cudaFuncAttributeMaxDynamicSharedMemorySize, SMEM_DYN);
    cudaFuncSetAttribute(gemm_f16<HIDDEN, OUTD, true>,
                         cudaFuncAttributeMaxDynamicSharedMemorySize, SMEM_DYN);

    // zero full output (non-active blocks must be 0)
    cudaMemsetAsync(d_out, 0, (size_t)out_size * sizeof(float));

    // fp16 conversions
    gather_convert<<<(MACT * (EMBED / 4)) / 256, 256>>>(x, nz, (__half*)pg);
    transpose_convert<<<dim3(HIDDEN / 32, EMBED / 32), dim3(32, 8)>>>(fc1, (__half*)pw1, EMBED, HIDDEN);
    transpose_convert<<<dim3(OUTD / 32, HIDDEN / 32), dim3(32, 8)>>>(fc2, (__half*)pw2, HIDDEN, OUTD);

    // GEMM1: h = g @ fc1^T-layout   (M=4096, N=16384, K=4096), m-fast grid
    gemm_f16<EMBED, HIDDEN, false>
        <<<dim3(MACT / BM, HIDDEN / BN), 256, SMEM_DYN>>>(
            (const __half*)pg, (const __half*)pw1, ph, nz);

    // GEMM2: out[nz] = h @ fc2^T-layout   (M=4096, N=4096, K=16384), fp32 scatter
    gemm_f16<HIDDEN, OUTD, true>
        <<<dim3(MACT / BM, OUTD / BN), 256, SMEM_DYN>>>(
            (const __half*)ph, (const __half*)pw2, d_out, nz);
}

// round 7
// speedup vs baseline: 1.5392x; 1.5392x over previous
#include <cuda_runtime.h>
#include <cuda_fp16.h>
#include <cstdint>
#include <cstddef>

// ---------------- problem dims (fixed by the dataset instance) ----------------
#define BLOCK   128
#define EMBED   4096
#define HIDDEN  16384
#define OUTD    4096
#define NZB     32
#define MACT    (NZB * BLOCK)   // 4096 active rows

// ---------------- scratch (device globals: allocation-free rule) -------------
__device__ __half d_g  [(size_t)MACT   * EMBED ];  // gathered activations fp16 [M,K]
__device__ __half d_w1t[(size_t)HIDDEN * EMBED ];  // fc1^T fp16 [N=HIDDEN, K=EMBED]
__device__ __half d_w2t[(size_t)OUTD   * HIDDEN];  // fc2^T fp16 [N=OUTD,   K=HIDDEN]
__device__ __half d_h  [(size_t)MACT   * HIDDEN];  // hidden fp16 [M,K2]

// ---------------- PTX helpers (all portable, sm_80-level) ---------------------
__device__ __forceinline__ uint32_t smem_u32(const void* p) {
    uint32_t a;
    asm("{ .reg .u64 t; cvta.to.shared.u64 t, %1; cvt.u32.u64 %0, t; }" : "=r"(a) : "l"(p));
    return a;
}
__device__ __forceinline__ void cp16(uint32_t dst, const void* src) {
    asm volatile("cp.async.cg.shared.global [%0], [%1], 16;" :: "r"(dst), "l"(src) : "memory");
}
#define CP_COMMIT()  asm volatile("cp.async.commit_group;" ::: "memory")
#define CP_WAIT1()   asm volatile("cp.async.wait_group 1;" ::: "memory")
#define SW128(o) ((o) ^ (((o) >> 3) & 0x70))

__device__ __forceinline__ void ldsm_x4(uint32_t* r, uint32_t addr) {
    asm volatile("ldmatrix.sync.aligned.m8n8.x4.shared.b16 {%0,%1,%2,%3}, [%4];"
                 : "=r"(r[0]), "=r"(r[1]), "=r"(r[2]), "=r"(r[3]) : "r"(addr));
}
__device__ __forceinline__ void ldsm_x2(uint32_t* r, uint32_t addr) {
    asm volatile("ldmatrix.sync.aligned.m8n8.x2.shared.b16 {%0,%1}, [%2];"
                 : "=r"(r[0]), "=r"(r[1]) : "r"(addr));
}
__device__ __forceinline__ void mma16816(float* c, const uint32_t* a, const uint32_t* b) {
    asm volatile(
        "mma.sync.aligned.m16n8k16.row.col.f32.f16.f16.f32 "
        "{%0,%1,%2,%3}, {%4,%5,%6,%7}, {%8,%9}, {%0,%1,%2,%3};"
        : "+f"(c[0]), "+f"(c[1]), "+f"(c[2]), "+f"(c[3])
        : "r"(a[0]), "r"(a[1]), "r"(a[2]), "r"(a[3]), "r"(b[0]), "r"(b[1]));
}

// ---------------- conversion kernels -----------------------------------------
__global__ void gather_convert(const float* __restrict__ x, const int* __restrict__ nz,
                               __half* __restrict__ g) {
    size_t idx  = (size_t)blockIdx.x * blockDim.x + threadIdx.x;  // over MACT*EMBED/4
    int    row  = (int)(idx >> 10);            // EMBED/4 = 1024 float4 per row
    int    col4 = (int)(idx & 1023);
    int    blk  = row >> 7;
    int    srow = nz[blk] * BLOCK + (row & 127);
    float4 v = reinterpret_cast<const float4*>(x)[(size_t)srow * (EMBED / 4) + col4];
    __half2* dst = reinterpret_cast<__half2*>(g + (size_t)row * EMBED + (size_t)col4 * 4);
    dst[0] = __floats2half2_rn(v.x, v.y);
    dst[1] = __floats2half2_rn(v.z, v.w);
}

// in [R,C] fp32 row-major -> out [C,R] fp16 row-major
__global__ void transpose_convert(const float* __restrict__ in, __half* __restrict__ out,
                                  int R, int C) {
    __shared__ float tile[32][33];
    int c0 = blockIdx.x * 32, r0 = blockIdx.y * 32;
    int tx = threadIdx.x, ty = threadIdx.y;  // (32,8)
#pragma unroll
    for (int i = 0; i < 4; i++) {
        int y = ty + i * 8;
        tile[y][tx] = in[(size_t)(r0 + y) * C + c0 + tx];
    }
    __syncthreads();
#pragma unroll
    for (int i = 0; i < 4; i++) {
        int y = ty + i * 8;
        out[(size_t)(c0 + y) * R + r0 + tx] = __float2half(tile[tx][y]);
    }
}

// ---------------- HMMA GEMM ---------------------------------------------------
// C[m,n] = sum_k A[m,k]*B[n,k]; A:[M,KTOT] fp16 K-major, B:[Ntot,KTOT] fp16 K-major.
// Grid: blockIdx.x = M-tile (fast), blockIdx.y = N-tile (slow) -> a 148-CTA wave
// shares ~5 B tiles + 32 A tiles through L2 (operands are L2-resident).
// CTA tile 128x128, BK=64 (SW128 rows), 4-stage cp.async, 1 CTA/SM (no spills).
// Fragment double-buffering hides LDSM latency under MMAs.
// 8 warps in a 2(m) x 4(n) grid; warp tile 64x32; mma.sync m16n8k16.
constexpr int BM = 128, BN = 128, BK = 64, STAGES = 4;
constexpr uint32_t ABYTES      = BM * BK * 2;          // 16384
constexpr uint32_t STAGE_BYTES = 2 * ABYTES;           // 32768
constexpr uint32_t SMEM_DYN    = STAGES * STAGE_BYTES; // 131072

__device__ __forceinline__ void load_frag_a(uint32_t (&a)[4][4], uint32_t sA,
                                            int wm, int lane, int ks) {
#pragma unroll
    for (int i = 0; i < 4; i++) {
        const uint32_t r  = (uint32_t)(wm * 64 + i * 16 + (lane & 15));
        const uint32_t cb = (uint32_t)(ks * 32 + ((lane >> 4) << 4));
        ldsm_x4(a[i], sA + SW128(r * 128 + cb));
    }
}
__device__ __forceinline__ void load_frag_b(uint32_t (&b)[4][2], uint32_t sB,
                                            int wn, int lane, int ks) {
#pragma unroll
    for (int j = 0; j < 4; j++) {
        const uint32_t r  = (uint32_t)(wn * 32 + j * 8 + (lane & 7));
        const uint32_t cb = (uint32_t)(ks * 32 + (((lane >> 3) & 1) << 4));
        ldsm_x2(b[j], sB + SW128(r * 128 + cb));
    }
}

template <int KTOT, int LDC, bool SCATTER>
__global__ void __launch_bounds__(256, 1)
gemm_f16(const __half* __restrict__ A, const __half* __restrict__ B,
         void* __restrict__ C, const int* __restrict__ nz) {
    extern __shared__ char smem[];
    const uint32_t sb = smem_u32(smem);
    const int tid  = threadIdx.x;
    const int lane = tid & 31, wid = tid >> 5;
    const int wm = wid >> 2, wn = wid & 3;             // 2 x 4 warp grid
    const int m0 = blockIdx.x * BM, n0 = blockIdx.y * BN;   // m-fast grid
    constexpr int KIT = KTOT / BK;

    // per-thread cp.async geometry: thread t covers row t/2, 64B half-row t%2
    const int lrow = tid >> 1;
    const int lcol = (tid & 1) * 64;                   // byte offset in 128B row
    const char* gA = (const char*)(A + (size_t)(m0 + lrow) * KTOT) + lcol;
    const char* gB = (const char*)(B + (size_t)(n0 + lrow) * KTOT) + lcol;
    const uint32_t swb = (uint32_t)(lrow * 128 + lcol);

    float acc[4][4][4];
#pragma unroll
    for (int i = 0; i < 4; i++)
#pragma unroll
        for (int j = 0; j < 4; j++)
#pragma unroll
            for (int q = 0; q < 4; q++) acc[i][j][q] = 0.f;

    // prologue: fill stages 0..STAGES-2 (3 commits)
#pragma unroll
    for (int s = 0; s < STAGES - 1; s++) {
        const uint32_t st = sb + (uint32_t)s * STAGE_BYTES;
        const size_t ko = (size_t)s * (BK * 2);
#pragma unroll
        for (int ch = 0; ch < 4; ch++)
            cp16(st + SW128(swb + ch * 16), gA + ko + ch * 16);
#pragma unroll
        for (int ch = 0; ch < 4; ch++)
            cp16(st + ABYTES + SW128(swb + ch * 16), gB + ko + ch * 16);
        CP_COMMIT();
    }

    uint32_t af[2][4][4], bf[2][4][2];   // double-buffered fragments

    for (int it = 0; it < KIT; it++) {
        // stages <= it+1 resident after this wait (groups: 3+it committed, <=1 pending)
        CP_WAIT1();
        __syncthreads();

        // issue stage it+3 into slot (it+3)&3 (disjoint from compute slot it&3);
        // commit every iter (possibly empty) to keep group numbering constant
        const int ls = it + STAGES - 1;
        if (ls < KIT) {
            const uint32_t st = sb + (uint32_t)(ls & (STAGES - 1)) * STAGE_BYTES;
            const size_t ko = (size_t)ls * (BK * 2);
#pragma unroll
            for (int ch = 0; ch < 4; ch++)
                cp16(st + SW128(swb + ch * 16), gA + ko + ch * 16);
#pragma unroll
            for (int ch = 0; ch < 4; ch++)
                cp16(st + ABYTES + SW128(swb + ch * 16), gB + ko + ch * 16);
        }
        CP_COMMIT();

        const uint32_t sA  = sb + (uint32_t)(it & (STAGES - 1)) * STAGE_BYTES;
        const uint32_t sBs = sA + ABYTES;

        if (it == 0) {             // prime buffer 0 (later iters arrive pre-loaded)
            load_frag_a(af[0], sA, wm, lane, 0);
            load_frag_b(bf[0], sBs, wn, lane, 0);
        }

#pragma unroll
        for (int ks = 0; ks < 4; ks++) {
            const int cur = ks & 1, nxt = cur ^ 1;
            if (ks < 3) {
                load_frag_a(af[nxt], sA, wm, lane, ks + 1);
                load_frag_b(bf[nxt], sBs, wn, lane, ks + 1);
            } else if (it + 1 < KIT) {
                // prefetch ks=0 of NEXT stage (resident per CP_WAIT1 above);
                // its slot is not rewritten until iter it+2's issue phase.
                const uint32_t nA = sb + (uint32_t)((it + 1) & (STAGES - 1)) * STAGE_BYTES;
                load_frag_a(af[nxt], nA, wm, lane, 0);
                load_frag_b(bf[nxt], nA + ABYTES, wn, lane, 0);
            }
#pragma unroll
            for (int i = 0; i < 4; i++)
#pragma unroll
                for (int j = 0; j < 4; j++)
                    mma16816(acc[i][j], af[cur][i], bf[cur][j]);
        }
    }

    // ---------------- epilogue ----------------
    // thread (i,j) frag: rows wm*64+i*16+lane/4 (+8), cols wn*32+j*8+2*(lane%4)
    const int rbase = wm * 64 + (lane >> 2);
    const int cbase = n0 + wn * 32 + 2 * (lane & 3);
    if (!SCATTER) {
        __half* Ch = (__half*)C;
#pragma unroll
        for (int i = 0; i < 4; i++) {
#pragma unroll
            for (int j = 0; j < 4; j++) {
                const int col = cbase + j * 8;
                const size_t r0 = (size_t)(m0 + rbase + i * 16) * LDC + col;
                const size_t r1 = r0 + (size_t)8 * LDC;
                *reinterpret_cast<__half2*>(Ch + r0) =
                    __floats2half2_rn(acc[i][j][0], acc[i][j][1]);
                *reinterpret_cast<__half2*>(Ch + r1) =
                    __floats2half2_rn(acc[i][j][2], acc[i][j][3]);
            }
        }
    } else {
        float* Cf = (float*)C;
        const int orow = nz[blockIdx.x] * BLOCK;   // m-tile (blockIdx.x) == source block
#pragma unroll
        for (int i = 0; i < 4; i++) {
#pragma unroll
            for (int j = 0; j < 4; j++) {
                const int col = cbase + j * 8;
                const size_t r0 = (size_t)(orow + rbase + i * 16) * LDC + col;
                const size_t r1 = r0 + (size_t)8 * LDC;
                *reinterpret_cast<float2*>(Cf + r0) =
                    make_float2(acc[i][j][0], acc[i][j][1]);
                *reinterpret_cast<float2*>(Cf + r1) =
                    make_float2(acc[i][j][2], acc[i][j][3]);
            }
        }
    }
}

// ---------------- launch ------------------------------------------------------
extern "C" void kernel_launch(void* const* d_in, const int* in_sizes, int n_in,
                              void* d_out, int out_size) {
    const float* x   = (const float*)d_in[0];
    const float* fc1 = (const float*)d_in[1];
    const float* fc2 = (const float*)d_in[2];
    const int*   nz  = (const int*)d_in[3];
    (void)in_sizes; (void)n_in;

    void *pg, *pw1, *pw2, *ph;
    cudaGetSymbolAddress(&pg,  d_g);
    cudaGetSymbolAddress(&pw1, d_w1t);
    cudaGetSymbolAddress(&pw2, d_w2t);
    cudaGetSymbolAddress(&ph,  d_h);

    cudaFuncSetAttribute(gemm_f16<EMBED, HIDDEN, false>,
                         cudaFuncAttributeMaxDynamicSharedMemorySize, SMEM_DYN);
    cudaFuncSetAttribute(gemm_f16<HIDDEN, OUTD, true>,
                         cudaFuncAttributeMaxDynamicSharedMemorySize, SMEM_DYN);

    // zero full output (non-active blocks must be 0)
    cudaMemsetAsync(d_out, 0, (size_t)out_size * sizeof(float));

    // fp16 conversions
    gather_convert<<<(MACT * (EMBED / 4)) / 256, 256>>>(x, nz, (__half*)pg);
    transpose_convert<<<dim3(HIDDEN / 32, EMBED / 32), dim3(32, 8)>>>(fc1, (__half*)pw1, EMBED, HIDDEN);
    transpose_convert<<<dim3(OUTD / 32, HIDDEN / 32), dim3(32, 8)>>>(fc2, (__half*)pw2, HIDDEN, OUTD);

    // GEMM1: h = g @ fc1^T-layout   (M=4096, N=16384, K=4096), m-fast grid
    gemm_f16<EMBED, HIDDEN, false>
        <<<dim3(MACT / BM, HIDDEN / BN), 256, SMEM_DYN>>>(
            (const __half*)pg, (const __half*)pw1, ph, nz);

    // GEMM2: out[nz] = h @ fc2^T-layout   (M=4096, N=4096, K=16384), fp32 scatter
    gemm_f16<HIDDEN, OUTD, true>
        <<<dim3(MACT / BM, OUTD / BN), 256, SMEM_DYN>>>(
            (const __half*)ph, (const __half*)pw2, d_out, nz);
}

// round 8
// speedup vs baseline: 1.5449x; 1.0037x over previous
#include <cuda_runtime.h>
#include <cuda_fp16.h>
#include <cstdint>
#include <cstddef>

// ---------------- problem dims (fixed by the dataset instance) ----------------
#define BLOCK   128
#define EMBED   4096
#define HIDDEN  16384
#define OUTD    4096
#define NZB     32
#define MACT    (NZB * BLOCK)   // 4096 active rows

// ---------------- scratch (device globals: allocation-free rule) -------------
__device__ __half d_g  [(size_t)MACT   * EMBED ];  // gathered activations fp16 [M,K]
__device__ __half d_w1t[(size_t)HIDDEN * EMBED ];  // fc1^T fp16 [N=HIDDEN, K=EMBED]
__device__ __half d_w2t[(size_t)OUTD   * HIDDEN];  // fc2^T fp16 [N=OUTD,   K=HIDDEN]
__device__ __half d_h  [(size_t)MACT   * HIDDEN];  // hidden fp16 [M,K2]

// ---------------- PTX helpers (all portable, sm_80-level) ---------------------
__device__ __forceinline__ uint32_t smem_u32(const void* p) {
    uint32_t a;
    asm("{ .reg .u64 t; cvta.to.shared.u64 t, %1; cvt.u32.u64 %0, t; }" : "=r"(a) : "l"(p));
    return a;
}
__device__ __forceinline__ void cp16(uint32_t dst, const void* src) {
    asm volatile("cp.async.cg.shared.global [%0], [%1], 16;" :: "r"(dst), "l"(src) : "memory");
}
#define CP_COMMIT()  asm volatile("cp.async.commit_group;" ::: "memory")
#define CP_WAIT1()   asm volatile("cp.async.wait_group 1;" ::: "memory")
#define SW128(o) ((o) ^ (((o) >> 3) & 0x70))

__device__ __forceinline__ void ldsm_x4(uint32_t* r, uint32_t addr) {
    asm volatile("ldmatrix.sync.aligned.m8n8.x4.shared.b16 {%0,%1,%2,%3}, [%4];"
                 : "=r"(r[0]), "=r"(r[1]), "=r"(r[2]), "=r"(r[3]) : "r"(addr));
}
__device__ __forceinline__ void ldsm_x2(uint32_t* r, uint32_t addr) {
    asm volatile("ldmatrix.sync.aligned.m8n8.x2.shared.b16 {%0,%1}, [%2];"
                 : "=r"(r[0]), "=r"(r[1]) : "r"(addr));
}
__device__ __forceinline__ void mma16816(float* c, const uint32_t* a, const uint32_t* b) {
    asm volatile(
        "mma.sync.aligned.m16n8k16.row.col.f32.f16.f16.f32 "
        "{%0,%1,%2,%3}, {%4,%5,%6,%7}, {%8,%9}, {%0,%1,%2,%3};"
        : "+f"(c[0]), "+f"(c[1]), "+f"(c[2]), "+f"(c[3])
        : "r"(a[0]), "r"(a[1]), "r"(a[2]), "r"(a[3]), "r"(b[0]), "r"(b[1]));
}

// ---------------- conversion kernels -----------------------------------------
__global__ void gather_convert(const float* __restrict__ x, const int* __restrict__ nz,
                               __half* __restrict__ g) {
    size_t idx  = (size_t)blockIdx.x * blockDim.x + threadIdx.x;  // over MACT*EMBED/4
    int    row  = (int)(idx >> 10);            // EMBED/4 = 1024 float4 per row
    int    col4 = (int)(idx & 1023);
    int    blk  = row >> 7;
    int    srow = nz[blk] * BLOCK + (row & 127);
    float4 v = reinterpret_cast<const float4*>(x)[(size_t)srow * (EMBED / 4) + col4];
    __half2* dst = reinterpret_cast<__half2*>(g + (size_t)row * EMBED + (size_t)col4 * 4);
    dst[0] = __floats2half2_rn(v.x, v.y);
    dst[1] = __floats2half2_rn(v.z, v.w);
}

// in [R,C] fp32 row-major -> out [C,R] fp16 row-major
__global__ void transpose_convert(const float* __restrict__ in, __half* __restrict__ out,
                                  int R, int C) {
    __shared__ float tile[32][33];
    int c0 = blockIdx.x * 32, r0 = blockIdx.y * 32;
    int tx = threadIdx.x, ty = threadIdx.y;  // (32,8)
#pragma unroll
    for (int i = 0; i < 4; i++) {
        int y = ty + i * 8;
        tile[y][tx] = in[(size_t)(r0 + y) * C + c0 + tx];
    }
    __syncthreads();
#pragma unroll
    for (int i = 0; i < 4; i++) {
        int y = ty + i * 8;
        out[(size_t)(c0 + y) * R + r0 + tx] = __float2half(tile[tx][y]);
    }
}

// ---------------- HMMA GEMM ---------------------------------------------------
// C[m,n] = sum_k A[m,k]*B[n,k]; A:[M,KTOT] fp16 K-major, B:[Ntot,KTOT] fp16 K-major.
// Grid: blockIdx.x = M-tile (fast) -> wave shares B tiles + A tiles through L2.
// CTA tile 128x128, BK=64 (SW128 rows), 4-stage cp.async, 512 threads:
// 16 warps in a 4(m) x 4(n) grid, warp tile 32x32 (~95 regs -> no spills,
// 4 warps per SMSP so the scheduler can cover LDSM/cp.async/barrier windows).
constexpr int BM = 128, BN = 128, BK = 64, STAGES = 4;
constexpr uint32_t ABYTES      = BM * BK * 2;          // 16384
constexpr uint32_t STAGE_BYTES = 2 * ABYTES;           // 32768
constexpr uint32_t SMEM_DYN    = STAGES * STAGE_BYTES; // 131072

// A fragments: 2 m16-tiles (rows wm*32 + i*16), x4 ldmatrix each
__device__ __forceinline__ void load_frag_a(uint32_t (&a)[2][4], uint32_t sA,
                                            int wm, int lane, int ks) {
#pragma unroll
    for (int i = 0; i < 2; i++) {
        const uint32_t r  = (uint32_t)(wm * 32 + i * 16 + (lane & 15));
        const uint32_t cb = (uint32_t)(ks * 32 + ((lane >> 4) << 4));
        ldsm_x4(a[i], sA + SW128(r * 128 + cb));
    }
}
// B fragments: 4 n8-tiles (rows wn*32 + j*8), x2 ldmatrix each
__device__ __forceinline__ void load_frag_b(uint32_t (&b)[4][2], uint32_t sB,
                                            int wn, int lane, int ks) {
#pragma unroll
    for (int j = 0; j < 4; j++) {
        const uint32_t r  = (uint32_t)(wn * 32 + j * 8 + (lane & 7));
        const uint32_t cb = (uint32_t)(ks * 32 + (((lane >> 3) & 1) << 4));
        ldsm_x2(b[j], sB + SW128(r * 128 + cb));
    }
}

template <int KTOT, int LDC, bool SCATTER>
__global__ void __launch_bounds__(512, 1)
gemm_f16(const __half* __restrict__ A, const __half* __restrict__ B,
         void* __restrict__ C, const int* __restrict__ nz) {
    extern __shared__ char smem[];
    const uint32_t sb = smem_u32(smem);
    const int tid  = threadIdx.x;
    const int lane = tid & 31, wid = tid >> 5;
    const int wm = wid >> 2, wn = wid & 3;             // 4 x 4 warp grid
    const int m0 = blockIdx.x * BM, n0 = blockIdx.y * BN;   // m-fast grid
    constexpr int KIT = KTOT / BK;

    // cp.async: 256 combined rows (0-127 = A, 128-255 = B), 2 threads per row,
    // each thread one 64B half-row (4 x 16B chunks)
    const int lrow = tid >> 1;                          // 0..255
    const int lcol = (tid & 1) * 64;
    const char* gsrc = (lrow < BM)
        ? (const char*)(A + (size_t)(m0 + lrow) * KTOT) + lcol
        : (const char*)(B + (size_t)(n0 + lrow - BM) * KTOT) + lcol;
    const uint32_t swb = (uint32_t)(lrow * 128 + lcol); // byte offset in 32KB stage

    float acc[2][4][4];
#pragma unroll
    for (int i = 0; i < 2; i++)
#pragma unroll
        for (int j = 0; j < 4; j++)
#pragma unroll
            for (int q = 0; q < 4; q++) acc[i][j][q] = 0.f;

    // prologue: fill stages 0..STAGES-2 (3 commits)
#pragma unroll
    for (int s = 0; s < STAGES - 1; s++) {
        const uint32_t st = sb + (uint32_t)s * STAGE_BYTES;
        const size_t ko = (size_t)s * (BK * 2);
#pragma unroll
        for (int ch = 0; ch < 4; ch++)
            cp16(st + SW128(swb + ch * 16), gsrc + ko + ch * 16);
        CP_COMMIT();
    }

    uint32_t af[2][2][4], bf[2][4][2];   // double-buffered fragments

    for (int it = 0; it < KIT; it++) {
        // stages <= it+1 resident after this wait (groups: 3+it committed, <=1 pending)
        CP_WAIT1();
        __syncthreads();

        // issue stage it+3 into slot (it+3)&3 (disjoint from compute slot it&3)
        const int ls = it + STAGES - 1;
        if (ls < KIT) {
            const uint32_t st = sb + (uint32_t)(ls & (STAGES - 1)) * STAGE_BYTES;
            const size_t ko = (size_t)ls * (BK * 2);
#pragma unroll
            for (int ch = 0; ch < 4; ch++)
                cp16(st + SW128(swb + ch * 16), gsrc + ko + ch * 16);
        }
        CP_COMMIT();

        const uint32_t sA  = sb + (uint32_t)(it & (STAGES - 1)) * STAGE_BYTES;
        const uint32_t sBs = sA + ABYTES;

        if (it == 0) {             // prime buffer 0 (later iters arrive pre-loaded)
            load_frag_a(af[0], sA, wm, lane, 0);
            load_frag_b(bf[0], sBs, wn, lane, 0);
        }

#pragma unroll
        for (int ks = 0; ks < 4; ks++) {
            const int cur = ks & 1, nxt = cur ^ 1;
            if (ks < 3) {
                load_frag_a(af[nxt], sA, wm, lane, ks + 1);
                load_frag_b(bf[nxt], sBs, wn, lane, ks + 1);
            } else if (it + 1 < KIT) {
                // prefetch ks=0 of NEXT stage (resident per CP_WAIT1 above);
                // its slot is not rewritten until iter it+2's issue phase.
                const uint32_t nA = sb + (uint32_t)((it + 1) & (STAGES - 1)) * STAGE_BYTES;
                load_frag_a(af[nxt], nA, wm, lane, 0);
                load_frag_b(bf[nxt], nA + ABYTES, wn, lane, 0);
            }
#pragma unroll
            for (int i = 0; i < 2; i++)
#pragma unroll
                for (int j = 0; j < 4; j++)
                    mma16816(acc[i][j], af[cur][i], bf[cur][j]);
        }
    }

    // ---------------- epilogue ----------------
    // frag (i,j): rows wm*32+i*16+lane/4 (+8), cols wn*32+j*8+2*(lane%4)
    const int rbase = wm * 32 + (lane >> 2);
    const int cbase = n0 + wn * 32 + 2 * (lane & 3);
    if (!SCATTER) {
        __half* Ch = (__half*)C;
#pragma unroll
        for (int i = 0; i < 2; i++) {
#pragma unroll
            for (int j = 0; j < 4; j++) {
                const int col = cbase + j * 8;
                const size_t r0 = (size_t)(m0 + rbase + i * 16) * LDC + col;
                const size_t r1 = r0 + (size_t)8 * LDC;
                *reinterpret_cast<__half2*>(Ch + r0) =
                    __floats2half2_rn(acc[i][j][0], acc[i][j][1]);
                *reinterpret_cast<__half2*>(Ch + r1) =
                    __floats2half2_rn(acc[i][j][2], acc[i][j][3]);
            }
        }
    } else {
        float* Cf = (float*)C;
        const int orow = nz[blockIdx.x] * BLOCK;   // m-tile (blockIdx.x) == source block
#pragma unroll
        for (int i = 0; i < 2; i++) {
#pragma unroll
            for (int j = 0; j < 4; j++) {
                const int col = cbase + j * 8;
                const size_t r0 = (size_t)(orow + rbase + i * 16) * LDC + col;
                const size_t r1 = r0 + (size_t)8 * LDC;
                *reinterpret_cast<float2*>(Cf + r0) =
                    make_float2(acc[i][j][0], acc[i][j][1]);
                *reinterpret_cast<float2*>(Cf + r1) =
                    make_float2(acc[i][j][2], acc[i][j][3]);
            }
        }
    }
}

// ---------------- launch ------------------------------------------------------
extern "C" void kernel_launch(void* const* d_in, const int* in_sizes, int n_in,
                              void* d_out, int out_size) {
    const float* x   = (const float*)d_in[0];
    const float* fc1 = (const float*)d_in[1];
    const float* fc2 = (const float*)d_in[2];
    const int*   nz  = (const int*)d_in[3];
    (void)in_sizes; (void)n_in;

    void *pg, *pw1, *pw2, *ph;
    cudaGetSymbolAddress(&pg,  d_g);
    cudaGetSymbolAddress(&pw1, d_w1t);
    cudaGetSymbolAddress(&pw2, d_w2t);
    cudaGetSymbolAddress(&ph,  d_h);

    cudaFuncSetAttribute(gemm_f16<EMBED, HIDDEN, false>,
                         cudaFuncAttributeMaxDynamicSharedMemorySize, SMEM_DYN);
    cudaFuncSetAttribute(gemm_f16<HIDDEN, OUTD, true>,
                         cudaFuncAttributeMaxDynamicSharedMemorySize, SMEM_DYN);

    // zero full output (non-active blocks must be 0)
    cudaMemsetAsync(d_out, 0, (size_t)out_size * sizeof(float));

    // fp16 conversions
    gather_convert<<<(MACT * (EMBED / 4)) / 256, 256>>>(x, nz, (__half*)pg);
    transpose_convert<<<dim3(HIDDEN / 32, EMBED / 32), dim3(32, 8)>>>(fc1, (__half*)pw1, EMBED, HIDDEN);
    transpose_convert<<<dim3(OUTD / 32, HIDDEN / 32), dim3(32, 8)>>>(fc2, (__half*)pw2, HIDDEN, OUTD);

    // GEMM1: h = g @ fc1^T-layout   (M=4096, N=16384, K=4096), m-fast grid
    gemm_f16<EMBED, HIDDEN, false>
        <<<dim3(MACT / BM, HIDDEN / BN), 512, SMEM_DYN>>>(
            (const __half*)pg, (const __half*)pw1, ph, nz);

    // GEMM2: out[nz] = h @ fc2^T-layout   (M=4096, N=4096, K=16384), fp32 scatter
    gemm_f16<HIDDEN, OUTD, true>
        <<<dim3(MACT / BM, OUTD / BN), 512, SMEM_DYN>>>(
            (const __half*)ph, (const __half*)pw2, d_out, nz);
}